// round 2
// baseline (speedup 1.0000x reference)
#include <cuda_runtime.h>
#include <math.h>

#define N_NODES 100000
#define N_EDGES 3200000
#define K_IN    1433
#define C1      16
#define C2      7

// ---------------- scratch (static device globals; no allocation) ------------
__device__ int   g_cnt[N_NODES];
__device__ int   g_off[N_NODES + 1];
__device__ int   g_pos[N_NODES];
__device__ float g_dinv[N_NODES];
__device__ int   g_ecol[N_EDGES];
__device__ float g_h1[N_NODES * 16];
__device__ float g_a1[N_NODES * 16];
__device__ float g_h2[N_NODES * 8];

// ---------------- degree / CSR build ---------------------------------------
__global__ void k_zero_cnt() {
    int i = blockIdx.x * blockDim.x + threadIdx.x;
    if (i < N_NODES) g_cnt[i] = 0;
}

__global__ void k_count(const int* __restrict__ row) {
    int e = blockIdx.x * blockDim.x + threadIdx.x;
    if (e < N_EDGES) atomicAdd(&g_cnt[row[e]], 1);
}

// single-block exclusive scan of counts -> offsets; also dinv = rsqrt(deg+1)
__global__ void k_scan() {
    const int T = 1024;
    const int CHUNK = (N_NODES + T - 1) / T;  // 98
    int t = threadIdx.x;
    int lo = t * CHUNK;
    int hi = min(lo + CHUNK, N_NODES);
    int sum = 0;
    for (int i = lo; i < hi; i++) sum += g_cnt[i];
    __shared__ int ps[T];
    ps[t] = sum;
    __syncthreads();
    for (int off = 1; off < T; off <<= 1) {
        int v = (t >= off) ? ps[t - off] : 0;
        __syncthreads();
        ps[t] += v;
        __syncthreads();
    }
    int run = (t > 0) ? ps[t - 1] : 0;
    for (int i = lo; i < hi; i++) {
        g_off[i] = run;
        g_pos[i] = run;
        run += g_cnt[i];
        g_dinv[i] = rsqrtf((float)(g_cnt[i] + 1));  // +1 self loop, always > 0
    }
    if (t == T - 1) g_off[N_NODES] = ps[T - 1];
}

__global__ void k_place(const int* __restrict__ row, const int* __restrict__ col) {
    int e = blockIdx.x * blockDim.x + threadIdx.x;
    if (e < N_EDGES) {
        int p = atomicAdd(&g_pos[row[e]], 1);
        g_ecol[p] = col[e];
    }
}

// ---------------- GEMM1: h1 = x @ W1  (100000x1433 @ 1433x16) ---------------
#define G1_BLOCK 256
#define G1_MT    680           // nodes per block -> exactly 148 blocks
#define G1_KT    8
#define G1_MTP   681           // padded row for bank-conflict avoidance
#define G1_R     3             // 3*256 >= 680
#define G1_NT    ((K_IN + G1_KT - 1) / G1_KT)       // 180
#define G1_LD    ((G1_MT * G1_KT + G1_BLOCK - 1) / G1_BLOCK)  // 22
#define WS_PAD_K 1440          // padded K for W (zero-filled tail)
// smem floats: W(1440*16) + 2 x-buffers(8*681) + overflow pad(128)
#define G1_SMEM_FLOATS (WS_PAD_K * C1 + 2 * G1_KT * G1_MTP + 128)
#define G1_SMEM_BYTES  (G1_SMEM_FLOATS * 4)

__global__ void __launch_bounds__(G1_BLOCK, 1)
k_gemm1(const float* __restrict__ x, const float* __restrict__ W1) {
    extern __shared__ float sm[];
    float* ws = sm;                       // [WS_PAD_K * 16]
    float* xs = sm + WS_PAD_K * C1;       // [2][G1_KT][G1_MTP] (+pad)

    const int tid = threadIdx.x;
    const int m0  = blockIdx.x * G1_MT;

    // load W1 into smem (zero-pad k >= 1433)
    {
        const float4* W4  = (const float4*)W1;
        float4*       ws4 = (float4*)ws;
        const int nW = K_IN * C1 / 4;          // 5732
        const int nP = WS_PAD_K * C1 / 4;      // 5760
        for (int i = tid; i < nP; i += G1_BLOCK) {
            float4 v = make_float4(0.f, 0.f, 0.f, 0.f);
            if (i < nW) v = W4[i];
            ws4[i] = v;
        }
    }

    float acc[G1_R][16];
#pragma unroll
    for (int r = 0; r < G1_R; r++)
#pragma unroll
        for (int c = 0; c < 16; c++) acc[r][c] = 0.f;

    float st[G1_LD];

    // prologue: load tile 0
#pragma unroll
    for (int u = 0; u < G1_LD; u++) {
        int i = tid + u * G1_BLOCK;
        float v = 0.f;
        if (i < G1_MT * G1_KT) {
            int k = i & (G1_KT - 1);
            int m = i >> 3;
            int gm = m0 + m, gk = k;
            if (gm < N_NODES && gk < K_IN) v = x[(size_t)gm * K_IN + gk];
        }
        st[u] = v;
    }
    // store tile 0 into buffer 0
#pragma unroll
    for (int u = 0; u < G1_LD; u++) {
        int i = tid + u * G1_BLOCK;
        if (i < G1_MT * G1_KT) {
            int k = i & (G1_KT - 1);
            int m = i >> 3;
            xs[k * G1_MTP + m] = st[u];
        }
    }
    __syncthreads();

    for (int t = 0; t < G1_NT; t++) {
        // prefetch tile t+1 into registers
        if (t + 1 < G1_NT) {
            int k0n = (t + 1) * G1_KT;
#pragma unroll
            for (int u = 0; u < G1_LD; u++) {
                int i = tid + u * G1_BLOCK;
                float v = 0.f;
                if (i < G1_MT * G1_KT) {
                    int k = i & (G1_KT - 1);
                    int m = i >> 3;
                    int gm = m0 + m, gk = k0n + k;
                    if (gm < N_NODES && gk < K_IN) v = x[(size_t)gm * K_IN + gk];
                }
                st[u] = v;
            }
        }

        // compute on buffer t&1
        const float* xb = xs + (t & 1) * (G1_KT * G1_MTP);
        const int k0 = t * G1_KT;
#pragma unroll
        for (int k = 0; k < G1_KT; k++) {
            const float4* wrow = (const float4*)(ws + (k0 + k) * C1);
            float4 w0 = wrow[0], w1 = wrow[1], w2 = wrow[2], w3 = wrow[3];
#pragma unroll
            for (int r = 0; r < G1_R; r++) {
                // lm may exceed G1_MT for r=2; reads land in the padded region,
                // results discarded at store time.
                float xv = xb[k * G1_MTP + (r * G1_BLOCK + tid)];
                acc[r][0]  += xv * w0.x;  acc[r][1]  += xv * w0.y;
                acc[r][2]  += xv * w0.z;  acc[r][3]  += xv * w0.w;
                acc[r][4]  += xv * w1.x;  acc[r][5]  += xv * w1.y;
                acc[r][6]  += xv * w1.z;  acc[r][7]  += xv * w1.w;
                acc[r][8]  += xv * w2.x;  acc[r][9]  += xv * w2.y;
                acc[r][10] += xv * w2.z;  acc[r][11] += xv * w2.w;
                acc[r][12] += xv * w3.x;  acc[r][13] += xv * w3.y;
                acc[r][14] += xv * w3.z;  acc[r][15] += xv * w3.w;
            }
        }
        __syncthreads();

        if (t + 1 < G1_NT) {
            float* xbn = xs + ((t + 1) & 1) * (G1_KT * G1_MTP);
#pragma unroll
            for (int u = 0; u < G1_LD; u++) {
                int i = tid + u * G1_BLOCK;
                if (i < G1_MT * G1_KT) {
                    int k = i & (G1_KT - 1);
                    int m = i >> 3;
                    xbn[k * G1_MTP + m] = st[u];
                }
            }
        }
        __syncthreads();
    }

    // write out
#pragma unroll
    for (int r = 0; r < G1_R; r++) {
        int lm = r * G1_BLOCK + tid;
        int m  = m0 + lm;
        if (lm < G1_MT && m < N_NODES) {
            float4* o = (float4*)(g_h1 + (size_t)m * 16);
            o[0] = make_float4(acc[r][0],  acc[r][1],  acc[r][2],  acc[r][3]);
            o[1] = make_float4(acc[r][4],  acc[r][5],  acc[r][6],  acc[r][7]);
            o[2] = make_float4(acc[r][8],  acc[r][9],  acc[r][10], acc[r][11]);
            o[3] = make_float4(acc[r][12], acc[r][13], acc[r][14], acc[r][15]);
        }
    }
}

// ---------------- aggregation 1 (+bias, +relu fused) -------------------------
// 16 lanes per node, lane = channel
__global__ void k_agg1(const float* __restrict__ b1) {
    int gid = blockIdx.x * blockDim.x + threadIdx.x;
    int g = gid >> 4;
    int c = gid & 15;
    if (g >= N_NODES) return;
    float di = g_dinv[g];
    float acc = b1[c] + g_h1[g * 16 + c] * di * di;   // self loop + bias
    int s = g_off[g], e = g_off[g + 1];
    for (int j = s; j < e; j++) {
        int cc = g_ecol[j];
        acc += g_h1[cc * 16 + c] * (di * g_dinv[cc]);
    }
    g_a1[g * 16 + c] = fmaxf(acc, 0.0f);              // relu fused
}

// ---------------- GEMM2: h2 = a1 @ W2 (16 -> 7), pad ch 7 with zero ----------
__global__ void k_gemm2(const float* __restrict__ W2) {
    __shared__ float ws[16 * 7];
    int tid = threadIdx.x;
    if (tid < 16 * 7) ws[tid] = W2[tid];
    __syncthreads();
    int i = blockIdx.x * blockDim.x + tid;
    if (i >= N_NODES) return;
    const float4* a4 = (const float4*)(g_a1 + (size_t)i * 16);
    float4 v0 = a4[0], v1 = a4[1], v2 = a4[2], v3 = a4[3];
    float v[16] = {v0.x, v0.y, v0.z, v0.w, v1.x, v1.y, v1.z, v1.w,
                   v2.x, v2.y, v2.z, v2.w, v3.x, v3.y, v3.z, v3.w};
    float acc[7] = {0.f, 0.f, 0.f, 0.f, 0.f, 0.f, 0.f};
#pragma unroll
    for (int k = 0; k < 16; k++)
#pragma unroll
        for (int c = 0; c < 7; c++) acc[c] += v[k] * ws[k * 7 + c];
    float* o = g_h2 + (size_t)i * 8;
#pragma unroll
    for (int c = 0; c < 7; c++) o[c] = acc[c];
    o[7] = 0.f;
}

// ---------------- aggregation 2 + bias + log_softmax fused -------------------
// 8 lanes per node; lane 7 is padding (h2 pad column is zero)
__global__ void k_agg2(const float* __restrict__ b2, float* __restrict__ out) {
    int gid = blockIdx.x * blockDim.x + threadIdx.x;
    int g = gid >> 3;
    int c = gid & 7;
    if (g >= N_NODES) return;
    float di = g_dinv[g];
    float acc = 0.f;
    if (c < 7) acc = b2[c] + g_h2[g * 8 + c] * di * di;
    int s = g_off[g], e = g_off[g + 1];
    for (int j = s; j < e; j++) {
        int cc = g_ecol[j];
        acc += g_h2[cc * 8 + c] * (di * g_dinv[cc]);  // lane 7 adds zeros
    }
    // log_softmax over the 7 valid lanes of this 8-lane group
    float mv = (c < 7) ? acc : -3.0e38f;
#pragma unroll
    for (int o = 4; o > 0; o >>= 1)
        mv = fmaxf(mv, __shfl_xor_sync(0xffffffffu, mv, o, 8));
    float ex = (c < 7) ? expf(acc - mv) : 0.f;
    float sum = ex;
#pragma unroll
    for (int o = 4; o > 0; o >>= 1)
        sum += __shfl_xor_sync(0xffffffffu, sum, o, 8);
    if (c < 7) out[(size_t)g * 7 + c] = acc - mv - logf(sum);
}

// ---------------- launch ------------------------------------------------------
extern "C" void kernel_launch(void* const* d_in, const int* in_sizes, int n_in,
                              void* d_out, int out_size) {
    const float* x   = (const float*)d_in[0];
    const int*   row = (const int*)  d_in[1];
    const int*   col = (const int*)  d_in[2];
    const float* W1  = (const float*)d_in[3];
    const float* b1  = (const float*)d_in[4];
    const float* W2  = (const float*)d_in[5];
    const float* b2  = (const float*)d_in[6];
    float* out = (float*)d_out;

    cudaFuncSetAttribute(k_gemm1, cudaFuncAttributeMaxDynamicSharedMemorySize,
                         G1_SMEM_BYTES);

    k_zero_cnt<<<(N_NODES + 255) / 256, 256>>>();
    k_count   <<<(N_EDGES + 255) / 256, 256>>>(row);
    k_scan    <<<1, 1024>>>();
    k_place   <<<(N_EDGES + 255) / 256, 256>>>(row, col);

    k_gemm1<<<(N_NODES + G1_MT - 1) / G1_MT, G1_BLOCK, G1_SMEM_BYTES>>>(x, W1);

    k_agg1 <<<(N_NODES * 16 + 255) / 256, 256>>>(b1);
    k_gemm2<<<(N_NODES + 127) / 128, 128>>>(W2);
    k_agg2 <<<(N_NODES * 8 + 255) / 256, 256>>>(b2, out);
}

// round 3
// speedup vs baseline: 1.2478x; 1.2478x over previous
#include <cuda_runtime.h>
#include <math.h>

#define N_NODES 100000
#define N_EDGES 3200000
#define K_IN    1433
#define C1      16

// ---------------- scratch (static device globals; no allocation) ------------
__device__ __align__(16) int   g_cnt[N_NODES];
__device__ __align__(16) int   g_off[N_NODES + 4];
__device__ __align__(16) int   g_pos[N_NODES];
__device__ __align__(16) float g_dinv[N_NODES];
__device__ __align__(16) int2  g_epack[N_EDGES];   // {col, bits(dinv[r]*dinv[c])}
__device__ __align__(16) float g_h1[N_NODES * 16];
__device__ __align__(16) float g_h2[N_NODES * 8];

// ---------------- degree / CSR build ---------------------------------------
__global__ void k_zero_cnt() {
    int i = blockIdx.x * blockDim.x + threadIdx.x;
    if (i * 4 < N_NODES) ((int4*)g_cnt)[i] = make_int4(0, 0, 0, 0);
}

__global__ void k_count(const int* __restrict__ row) {
    int i = blockIdx.x * blockDim.x + threadIdx.x;     // i*4 < N_EDGES exactly
    int4 r = ((const int4*)row)[i];
    atomicAdd(&g_cnt[r.x], 1);
    atomicAdd(&g_cnt[r.y], 1);
    atomicAdd(&g_cnt[r.z], 1);
    atomicAdd(&g_cnt[r.w], 1);
}

// single-block exclusive scan of counts -> offsets; also dinv = rsqrt(deg+1)
__global__ void k_scan() {
    const int T = 1024, ACT = 1000, CH4 = 25;          // 1000*100 = 100000
    int t = threadIdx.x;
    __shared__ int ps[T];
    int sum = 0;
    if (t < ACT) {
        const int4* c4 = (const int4*)g_cnt + t * CH4;
#pragma unroll
        for (int i = 0; i < CH4; i++) { int4 v = c4[i]; sum += v.x + v.y + v.z + v.w; }
    }
    ps[t] = sum;
    __syncthreads();
    for (int off = 1; off < T; off <<= 1) {
        int v = (t >= off) ? ps[t - off] : 0;
        __syncthreads();
        ps[t] += v;
        __syncthreads();
    }
    if (t < ACT) {
        int run = (t > 0) ? ps[t - 1] : 0;
        const int4* c4 = (const int4*)g_cnt + t * CH4;
        int4*   o4 = (int4*)g_off + t * CH4;
        int4*   p4 = (int4*)g_pos + t * CH4;
        float4* d4 = (float4*)g_dinv + t * CH4;
#pragma unroll 5
        for (int i = 0; i < CH4; i++) {
            int4 v = c4[i];
            int4 o;
            o.x = run; o.y = o.x + v.x; o.z = o.y + v.y; o.w = o.z + v.z;
            run = o.w + v.w;
            o4[i] = o; p4[i] = o;
            float4 dv;
            dv.x = rsqrtf((float)(v.x + 1)); dv.y = rsqrtf((float)(v.y + 1));
            dv.z = rsqrtf((float)(v.z + 1)); dv.w = rsqrtf((float)(v.w + 1));
            d4[i] = dv;
        }
        if (t == ACT - 1) g_off[N_NODES] = run;
    }
}

__global__ void k_place(const int* __restrict__ row, const int* __restrict__ col) {
    int i = blockIdx.x * blockDim.x + threadIdx.x;
    int4 r = ((const int4*)row)[i];
    int4 c = ((const int4*)col)[i];
    float w0 = g_dinv[r.x] * g_dinv[c.x];
    float w1 = g_dinv[r.y] * g_dinv[c.y];
    float w2 = g_dinv[r.z] * g_dinv[c.z];
    float w3 = g_dinv[r.w] * g_dinv[c.w];
    int p0 = atomicAdd(&g_pos[r.x], 1);
    int p1 = atomicAdd(&g_pos[r.y], 1);
    int p2 = atomicAdd(&g_pos[r.z], 1);
    int p3 = atomicAdd(&g_pos[r.w], 1);
    g_epack[p0] = make_int2(c.x, __float_as_int(w0));
    g_epack[p1] = make_int2(c.y, __float_as_int(w1));
    g_epack[p2] = make_int2(c.z, __float_as_int(w2));
    g_epack[p3] = make_int2(c.w, __float_as_int(w3));
}

// ---------------- GEMM1: h1 = x @ W1  (100000x1433 @ 1433x16) ---------------
#define G1_BLOCK 256
#define G1_MT    680
#define G1_KT    8
#define G1_MTP   681
#define G1_R     3
#define G1_NT    ((K_IN + G1_KT - 1) / G1_KT)
#define G1_LD    ((G1_MT * G1_KT + G1_BLOCK - 1) / G1_BLOCK)
#define WS_PAD_K 1440
#define G1_SMEM_FLOATS (WS_PAD_K * C1 + 2 * G1_KT * G1_MTP + 128)
#define G1_SMEM_BYTES  (G1_SMEM_FLOATS * 4)

__device__ __forceinline__ void ffma2(unsigned long long& d,
                                      unsigned long long a,
                                      unsigned long long b) {
    asm("fma.rn.f32x2 %0, %1, %2, %0;" : "+l"(d) : "l"(a), "l"(b));
}

__global__ void __launch_bounds__(G1_BLOCK, 1)
k_gemm1(const float* __restrict__ x, const float* __restrict__ W1) {
    extern __shared__ float sm[];
    float* ws = sm;                       // [WS_PAD_K * 16]
    float* xs = sm + WS_PAD_K * C1;       // [2][G1_KT][G1_MTP]

    const int tid = threadIdx.x;
    const int m0  = blockIdx.x * G1_MT;

    {
        const float4* W4  = (const float4*)W1;
        float4*       ws4 = (float4*)ws;
        const int nW = K_IN * C1 / 4;
        const int nP = WS_PAD_K * C1 / 4;
        for (int i = tid; i < nP; i += G1_BLOCK) {
            float4 v = make_float4(0.f, 0.f, 0.f, 0.f);
            if (i < nW) v = W4[i];
            ws4[i] = v;
        }
    }

    unsigned long long acc2[G1_R][8];
#pragma unroll
    for (int r = 0; r < G1_R; r++)
#pragma unroll
        for (int c = 0; c < 8; c++) acc2[r][c] = 0ull;

    float st[G1_LD];

#pragma unroll
    for (int u = 0; u < G1_LD; u++) {
        int i = tid + u * G1_BLOCK;
        float v = 0.f;
        if (i < G1_MT * G1_KT) {
            int k = i & (G1_KT - 1);
            int m = i >> 3;
            int gm = m0 + m, gk = k;
            if (gm < N_NODES && gk < K_IN) v = x[(size_t)gm * K_IN + gk];
        }
        st[u] = v;
    }
#pragma unroll
    for (int u = 0; u < G1_LD; u++) {
        int i = tid + u * G1_BLOCK;
        if (i < G1_MT * G1_KT) {
            int k = i & (G1_KT - 1);
            int m = i >> 3;
            xs[k * G1_MTP + m] = st[u];
        }
    }
    __syncthreads();

    for (int t = 0; t < G1_NT; t++) {
        if (t + 1 < G1_NT) {
            int k0n = (t + 1) * G1_KT;
#pragma unroll
            for (int u = 0; u < G1_LD; u++) {
                int i = tid + u * G1_BLOCK;
                float v = 0.f;
                if (i < G1_MT * G1_KT) {
                    int k = i & (G1_KT - 1);
                    int m = i >> 3;
                    int gm = m0 + m, gk = k0n + k;
                    if (gm < N_NODES && gk < K_IN) v = x[(size_t)gm * K_IN + gk];
                }
                st[u] = v;
            }
        }

        const float* xb = xs + (t & 1) * (G1_KT * G1_MTP);
        const int k0 = t * G1_KT;
#pragma unroll
        for (int k = 0; k < G1_KT; k++) {
            const ulonglong2* wrow = (const ulonglong2*)(ws + (k0 + k) * C1);
            ulonglong2 wa = wrow[0], wb = wrow[1], wc = wrow[2], wd = wrow[3];
#pragma unroll
            for (int r = 0; r < G1_R; r++) {
                float xv = xb[k * G1_MTP + (r * G1_BLOCK + tid)];
                unsigned long long xv2;
                asm("mov.b64 %0, {%1, %1};" : "=l"(xv2) : "f"(xv));
                ffma2(acc2[r][0], xv2, wa.x);
                ffma2(acc2[r][1], xv2, wa.y);
                ffma2(acc2[r][2], xv2, wb.x);
                ffma2(acc2[r][3], xv2, wb.y);
                ffma2(acc2[r][4], xv2, wc.x);
                ffma2(acc2[r][5], xv2, wc.y);
                ffma2(acc2[r][6], xv2, wd.x);
                ffma2(acc2[r][7], xv2, wd.y);
            }
        }
        __syncthreads();

        if (t + 1 < G1_NT) {
            float* xbn = xs + ((t + 1) & 1) * (G1_KT * G1_MTP);
#pragma unroll
            for (int u = 0; u < G1_LD; u++) {
                int i = tid + u * G1_BLOCK;
                if (i < G1_MT * G1_KT) {
                    int k = i & (G1_KT - 1);
                    int m = i >> 3;
                    xbn[k * G1_MTP + m] = st[u];
                }
            }
        }
        __syncthreads();
    }

#pragma unroll
    for (int r = 0; r < G1_R; r++) {
        int lm = r * G1_BLOCK + tid;
        int m  = m0 + lm;
        if (lm < G1_MT && m < N_NODES) {
            float4* o = (float4*)(g_h1 + (size_t)m * 16);
#pragma unroll
            for (int p = 0; p < 4; p++) {
                float2 f0, f1;
                asm("mov.b64 {%0, %1}, %2;" : "=f"(f0.x), "=f"(f0.y) : "l"(acc2[r][2 * p]));
                asm("mov.b64 {%0, %1}, %2;" : "=f"(f1.x), "=f"(f1.y) : "l"(acc2[r][2 * p + 1]));
                o[p] = make_float4(f0.x, f0.y, f1.x, f1.y);
            }
        }
    }
}

// -------- aggregation 1 + bias + relu + GEMM2 fused (4 lanes/node) ----------
__global__ void __launch_bounds__(256)
k_agg1(const float* __restrict__ b1, const float* __restrict__ W2) {
    __shared__ float w2s[16 * 7];
    if (threadIdx.x < 16 * 7) w2s[threadIdx.x] = W2[threadIdx.x];
    __syncthreads();

    int gid = blockIdx.x * blockDim.x + threadIdx.x;
    int g = gid >> 2;
    int q = gid & 3;
    bool valid = (g < N_NODES);
    if (g >= N_NODES) g = N_NODES - 1;

    float di = g_dinv[g];
    float dd = di * di;
    float4 acc = __ldg((const float4*)(g_h1 + (size_t)g * 16 + q * 4));
    float4 bb  = ((const float4*)b1)[q];
    acc.x = bb.x + acc.x * dd;
    acc.y = bb.y + acc.y * dd;
    acc.z = bb.z + acc.z * dd;
    acc.w = bb.w + acc.w * dd;

    int s = g_off[g], e = g_off[g + 1];
#pragma unroll 4
    for (int j = s; j < e; j++) {
        int2 pr = g_epack[j];
        float w = __int_as_float(pr.y);
        float4 hv = __ldg((const float4*)(g_h1 + (size_t)pr.x * 16 + q * 4));
        acc.x += hv.x * w; acc.y += hv.y * w;
        acc.z += hv.z * w; acc.w += hv.w * w;
    }

    // relu
    float v0 = fmaxf(acc.x, 0.f), v1 = fmaxf(acc.y, 0.f);
    float v2 = fmaxf(acc.z, 0.f), v3 = fmaxf(acc.w, 0.f);

    // fused GEMM2: lane q holds channels 4q..4q+3
    float h2a[7];
    const float* w2r = w2s + (4 * q) * 7;
#pragma unroll
    for (int c2 = 0; c2 < 7; c2++)
        h2a[c2] = v0 * w2r[c2] + v1 * w2r[7 + c2] + v2 * w2r[14 + c2] + v3 * w2r[21 + c2];
#pragma unroll
    for (int o = 1; o <= 2; o <<= 1)
#pragma unroll
        for (int c2 = 0; c2 < 7; c2++)
            h2a[c2] += __shfl_xor_sync(0xffffffffu, h2a[c2], o, 4);

    if (valid) {
        if (q == 0)
            *(float4*)(g_h2 + (size_t)g * 8) = make_float4(h2a[0], h2a[1], h2a[2], h2a[3]);
        else if (q == 1)
            *(float4*)(g_h2 + (size_t)g * 8 + 4) = make_float4(h2a[4], h2a[5], h2a[6], 0.f);
    }
}

// -------- aggregation 2 + bias + log_softmax fused (4 lanes x 2 ch) ---------
__global__ void __launch_bounds__(256)
k_agg2(const float* __restrict__ b2, float* __restrict__ out) {
    int gid = blockIdx.x * blockDim.x + threadIdx.x;
    int g = gid >> 2;
    int q = gid & 3;
    bool valid = (g < N_NODES);
    if (g >= N_NODES) g = N_NODES - 1;

    int c0 = 2 * q;
    float di = g_dinv[g];
    float dd = di * di;
    float2 self = *(const float2*)(g_h2 + (size_t)g * 8 + c0);
    float bb0 = b2[c0];                           // c0 <= 6 always
    float bb1 = (c0 + 1 < 7) ? b2[c0 + 1] : 0.f;
    float a0 = bb0 + self.x * dd;
    float a1 = bb1 + self.y * dd;

    int s = g_off[g], e = g_off[g + 1];
#pragma unroll 4
    for (int j = s; j < e; j++) {
        int2 pr = g_epack[j];
        float w = __int_as_float(pr.y);
        float2 hv = __ldg((const float2*)(g_h2 + (size_t)pr.x * 8 + c0));
        a0 += hv.x * w;
        a1 += hv.y * w;
    }

    // log_softmax over 7 valid channels (q==3 lane's a1 is pad)
    float m = (q == 3) ? a0 : fmaxf(a0, a1);
    m = fmaxf(m, __shfl_xor_sync(0xffffffffu, m, 1, 4));
    m = fmaxf(m, __shfl_xor_sync(0xffffffffu, m, 2, 4));
    float e0 = expf(a0 - m);
    float e1 = (q == 3) ? 0.f : expf(a1 - m);
    float ss = e0 + e1;
    ss += __shfl_xor_sync(0xffffffffu, ss, 1, 4);
    ss += __shfl_xor_sync(0xffffffffu, ss, 2, 4);
    float ls = m + logf(ss);

    if (valid) {
        out[(size_t)g * 7 + c0] = a0 - ls;
        if (q < 3) out[(size_t)g * 7 + c0 + 1] = a1 - ls;
    }
}

// ---------------- launch ------------------------------------------------------
extern "C" void kernel_launch(void* const* d_in, const int* in_sizes, int n_in,
                              void* d_out, int out_size) {
    const float* x   = (const float*)d_in[0];
    const int*   row = (const int*)  d_in[1];
    const int*   col = (const int*)  d_in[2];
    const float* W1  = (const float*)d_in[3];
    const float* b1  = (const float*)d_in[4];
    const float* W2  = (const float*)d_in[5];
    const float* b2  = (const float*)d_in[6];
    float* out = (float*)d_out;

    cudaFuncSetAttribute(k_gemm1, cudaFuncAttributeMaxDynamicSharedMemorySize,
                         G1_SMEM_BYTES);

    k_zero_cnt<<<(N_NODES / 4 + 255) / 256, 256>>>();
    k_count   <<<N_EDGES / 4 / 256, 256>>>(row);
    k_scan    <<<1, 1024>>>();
    k_place   <<<N_EDGES / 4 / 256, 256>>>(row, col);

    k_gemm1<<<(N_NODES + G1_MT - 1) / G1_MT, G1_BLOCK, G1_SMEM_BYTES>>>(x, W1);

    k_agg1 <<<(N_NODES * 4 + 255) / 256, 256>>>(b1, W2);
    k_agg2 <<<(N_NODES * 4 + 255) / 256, 256>>>(b2, out);
}